// round 8
// baseline (speedup 1.0000x reference)
#include <cuda_runtime.h>
#include <cuda_bf16.h>
#include <math.h>

// reconstruction_loss: Charbonnier mean over MSFA(4)-mosaic-gathered pixels.
//   X, Y: [B=8, C=16, H=512, W=512] fp32; c = (h%4)*4 + (w%4)
//   out = mean_{b,h,w} sqrt((X[b,c,h,w]-Y[b,c,h,w])^2 + 1e-6)
//
// R7: same single-wave 262144-thread shape and immediate-offset front-batched
// loads as R6 (16 independent LDG [R+imm] per thread), but 2048 blocks x 128
// threads to halve the wave-imbalance granularity (13.84 blocks/SM vs 6.92:
// the straggler SM overshoot drops from ~1/7 to ~1/14 of the load phase).
// Deterministic fixed-point (x2^32) u64 atomic reduction; last block writes
// the scalar and resets state for the next graph replay.

#define BLOCKS   2048
#define THREADS  128
#define ITERS    8
#define TOTAL_PIX 2097152u                 // 8*512*512
#define KSTRIDE  2048u                     // 4 rows * 512 floats = 8 KiB
#define FIXSCALE 4294967296.0              // 2^32

__device__ unsigned long long g_acc;       // zero-init at module load
__device__ unsigned int       g_count;

__global__ void __launch_bounds__(THREADS)
msfa_charbonnier_fused(const float* __restrict__ X,
                       const float* __restrict__ Y,
                       float* __restrict__ out) {
    unsigned tid = blockIdx.x * THREADS + threadIdx.x;   // < 2^18

    // tid -> (b, hlow, hm, w); thread covers h = hlow + 32*hm + 4k, k=0..7
    unsigned w    = tid & 511u;
    unsigned t    = tid >> 9;
    unsigned hm   = t & 15u;
    unsigned hlow = (t >> 4) & 3u;
    unsigned b    = t >> 6;                 // [0,8)

    unsigned c    = (hlow << 2) | (w & 3u);     // mosaic channel (k-invariant)
    unsigned off0 = (((b << 4) | c) << 18)      // plane base
                  | ((hlow + (hm << 5)) << 9)   // row h(k=0)
                  | w;

    const float* xp = X + off0;
    const float* yp = Y + off0;

    // 16 independent loads, one base register each tensor, immediate offsets.
    float xv[ITERS], yv[ITERS];
#pragma unroll
    for (int k = 0; k < ITERS; k++)
        xv[k] = __ldg(xp + (unsigned)k * KSTRIDE);
#pragma unroll
    for (int k = 0; k < ITERS; k++)
        yv[k] = __ldg(yp + (unsigned)k * KSTRIDE);

    float acc = 0.0f;
#pragma unroll
    for (int k = 0; k < ITERS; k++) {
        float d = xv[k] - yv[k];
        acc += sqrtf(fmaf(d, d, 1e-6f));
    }

    // warp reduce
#pragma unroll
    for (int s = 16; s > 0; s >>= 1)
        acc += __shfl_xor_sync(0xffffffffu, acc, s);

    __shared__ float sm[THREADS / 32];
    if ((threadIdx.x & 31u) == 0u)
        sm[threadIdx.x >> 5] = acc;
    __syncthreads();

    if (threadIdx.x == 0) {
        float p = sm[0] + sm[1] + sm[2] + sm[3];

        // Fixed-point accumulate: integer adds commute -> deterministic.
        unsigned long long q =
            (unsigned long long)__double2ll_rn((double)p * FIXSCALE);
        atomicAdd(&g_acc, q);
        __threadfence();

        unsigned prev = atomicAdd(&g_count, 1u);
        if (prev == BLOCKS - 1) {
            __threadfence();
            unsigned long long s = *(volatile unsigned long long*)&g_acc;
            double sum = (double)(long long)s * (1.0 / FIXSCALE);
            out[0] = (float)(sum / (double)TOTAL_PIX);
            // Reset for the next graph replay.
            g_acc   = 0ULL;
            g_count = 0u;
        }
    }
}

extern "C" void kernel_launch(void* const* d_in, const int* in_sizes, int n_in,
                              void* d_out, int out_size) {
    const float* X = (const float*)d_in[0];
    const float* Y = (const float*)d_in[1];
    float* out = (float*)d_out;

    msfa_charbonnier_fused<<<BLOCKS, THREADS>>>(X, Y, out);
}

// round 9
// speedup vs baseline: 1.1341x; 1.1341x over previous
#include <cuda_runtime.h>
#include <cuda_bf16.h>
#include <math.h>

// reconstruction_loss: Charbonnier mean over MSFA(4)-mosaic-gathered pixels.
//   X, Y: [B=8, C=16, H=512, W=512] fp32; c = (h%4)*4 + (w%4)
//   out = mean_{b,h,w} sqrt((X[b,c,h,w]-Y[b,c,h,w])^2 + 1e-6)
//
// R8 = R6 (best: 1024x256, 8 pixels/thread walking h in steps of 4, all 16
// loads immediate-offset front-batched) + tail trims:
//   - X/Y loads interleaved pairwise (still 16 independent LDG [R+imm])
//   - sqrt.approx.f32 (one MUFU) instead of IEEE sqrtf sequence
//   - two accumulators to halve the FADD dependency chain
// Deterministic fixed-point (x2^32) u64 atomic reduction; last block writes
// the scalar and resets state for the next graph replay.

#define BLOCKS   1024
#define THREADS  256
#define ITERS    8
#define TOTAL_PIX 2097152u                 // 8*512*512
#define KSTRIDE  2048u                     // 4 rows * 512 floats = 8 KiB
#define FIXSCALE 4294967296.0              // 2^32

__device__ unsigned long long g_acc;       // zero-init at module load
__device__ unsigned int       g_count;

__device__ __forceinline__ float fast_sqrt(float x) {
    float r;
    asm("sqrt.approx.f32 %0, %1;" : "=f"(r) : "f"(x));
    return r;
}

__global__ void __launch_bounds__(THREADS, 8)
msfa_charbonnier_fused(const float* __restrict__ X,
                       const float* __restrict__ Y,
                       float* __restrict__ out) {
    unsigned tid = blockIdx.x * THREADS + threadIdx.x;   // < 2^18

    // tid -> (b, hlow, hm, w); thread covers h = hlow + 32*hm + 4k, k=0..7
    unsigned w    = tid & 511u;
    unsigned t    = tid >> 9;
    unsigned hm   = t & 15u;
    unsigned hlow = (t >> 4) & 3u;
    unsigned b    = t >> 6;                 // [0,8)

    unsigned c    = (hlow << 2) | (w & 3u);     // mosaic channel (k-invariant)
    unsigned off0 = (((b << 4) | c) << 18)      // plane base
                  | ((hlow + (hm << 5)) << 9)   // row h(k=0)
                  | w;

    const float* xp = X + off0;
    const float* yp = Y + off0;

    // 16 independent loads, immediate offsets, X/Y pairwise interleaved.
    float xv[ITERS], yv[ITERS];
#pragma unroll
    for (int k = 0; k < ITERS; k++) {
        xv[k] = __ldg(xp + (unsigned)k * KSTRIDE);
        yv[k] = __ldg(yp + (unsigned)k * KSTRIDE);
    }

    float acc0 = 0.0f, acc1 = 0.0f;
#pragma unroll
    for (int k = 0; k < ITERS; k += 2) {
        float d0 = xv[k]     - yv[k];
        float d1 = xv[k + 1] - yv[k + 1];
        acc0 += fast_sqrt(fmaf(d0, d0, 1e-6f));
        acc1 += fast_sqrt(fmaf(d1, d1, 1e-6f));
    }
    float acc = acc0 + acc1;

    // warp reduce
#pragma unroll
    for (int s = 16; s > 0; s >>= 1)
        acc += __shfl_xor_sync(0xffffffffu, acc, s);

    __shared__ float sm[THREADS / 32];
    if ((threadIdx.x & 31u) == 0u)
        sm[threadIdx.x >> 5] = acc;
    __syncthreads();

    if (threadIdx.x == 0) {
        float p = 0.0f;
#pragma unroll
        for (int i = 0; i < THREADS / 32; i++)
            p += sm[i];

        // Fixed-point accumulate: integer adds commute -> deterministic.
        unsigned long long q =
            (unsigned long long)__double2ll_rn((double)p * FIXSCALE);
        atomicAdd(&g_acc, q);
        __threadfence();

        unsigned prev = atomicAdd(&g_count, 1u);
        if (prev == BLOCKS - 1) {
            __threadfence();
            unsigned long long s = *(volatile unsigned long long*)&g_acc;
            double sum = (double)(long long)s * (1.0 / FIXSCALE);
            out[0] = (float)(sum / (double)TOTAL_PIX);
            // Reset for the next graph replay.
            g_acc   = 0ULL;
            g_count = 0u;
        }
    }
}

extern "C" void kernel_launch(void* const* d_in, const int* in_sizes, int n_in,
                              void* d_out, int out_size) {
    const float* X = (const float*)d_in[0];
    const float* Y = (const float*)d_in[1];
    float* out = (float*)d_out;

    msfa_charbonnier_fused<<<BLOCKS, THREADS>>>(X, Y, out);
}

// round 11
// speedup vs baseline: 1.4301x; 1.2610x over previous
#include <cuda_runtime.h>
#include <cuda_bf16.h>
#include <math.h>

// reconstruction_loss: Charbonnier mean over MSFA(4)-mosaic-gathered pixels.
//   X, Y: [B=8, C=16, H=512, W=512] fp32; c = (h%4)*4 + (w%4)
//   out = mean_{b,h,w} sqrt((X[b,c,h,w]-Y[b,c,h,w])^2 + 1e-6)
//
// R9 = R6 load structure (1024x256 single wave, 8 pixels/thread walking h in
// steps of 4; two front-batched groups of 8 immediate-offset LDGs) +
//   - sqrt.approx.f32 (1 MUFU; rel err ~1e-7 << 1e-3 tolerance)
//   - ONE-atomic finalize: 64-bit fixed-point sum with the block-arrival
//     counter packed into the low 12 bits. The 1024th arriver's atomicAdd
//     return value IS the complete total -> no fence, no second atomic.
//     Deterministic: integer adds commute.

#define BLOCKS   1024
#define THREADS  256
#define ITERS    8
#define TOTAL_PIX 2097152u                 // 8*512*512
#define KSTRIDE  2048u                     // 4 rows * 512 floats = 8 KiB
#define FIXSCALE 4294967296.0              // 2^32
#define CNT_MASK 0xFFFULL                  // low 12 bits = arrival count

__device__ unsigned long long g_acc;       // zero-init at module load

__device__ __forceinline__ float fast_sqrt(float x) {
    float r;
    asm("sqrt.approx.f32 %0, %1;" : "=f"(r) : "f"(x));
    return r;
}

__global__ void __launch_bounds__(THREADS, 8)
msfa_charbonnier_fused(const float* __restrict__ X,
                       const float* __restrict__ Y,
                       float* __restrict__ out) {
    unsigned tid = blockIdx.x * THREADS + threadIdx.x;   // < 2^18

    // tid -> (b, hlow, hm, w); thread covers h = hlow + 32*hm + 4k, k=0..7
    unsigned w    = tid & 511u;
    unsigned t    = tid >> 9;
    unsigned hm   = t & 15u;
    unsigned hlow = (t >> 4) & 3u;
    unsigned b    = t >> 6;                 // [0,8)

    unsigned c    = (hlow << 2) | (w & 3u);     // mosaic channel (k-invariant)
    unsigned off0 = (((b << 4) | c) << 18)      // plane base
                  | ((hlow + (hm << 5)) << 9)   // row h(k=0)
                  | w;

    const float* xp = X + off0;
    const float* yp = Y + off0;

    // 16 independent loads: two front-batched groups, immediate offsets only.
    float xv[ITERS], yv[ITERS];
#pragma unroll
    for (int k = 0; k < ITERS; k++)
        xv[k] = __ldg(xp + (unsigned)k * KSTRIDE);
#pragma unroll
    for (int k = 0; k < ITERS; k++)
        yv[k] = __ldg(yp + (unsigned)k * KSTRIDE);

    float acc0 = 0.0f, acc1 = 0.0f;
#pragma unroll
    for (int k = 0; k < ITERS; k += 2) {
        float d0 = xv[k]     - yv[k];
        float d1 = xv[k + 1] - yv[k + 1];
        acc0 += fast_sqrt(fmaf(d0, d0, 1e-6f));
        acc1 += fast_sqrt(fmaf(d1, d1, 1e-6f));
    }
    float acc = acc0 + acc1;

    // warp reduce
#pragma unroll
    for (int s = 16; s > 0; s >>= 1)
        acc += __shfl_xor_sync(0xffffffffu, acc, s);

    __shared__ float sm[THREADS / 32];
    if ((threadIdx.x & 31u) == 0u)
        sm[threadIdx.x >> 5] = acc;
    __syncthreads();

    if (threadIdx.x == 0) {
        float p = 0.0f;
#pragma unroll
        for (int i = 0; i < THREADS / 32; i++)
            p += sm[i];

        // Fixed-point block partial (x 2^32), low 12 bits ceded to counter.
        unsigned long long q =
            (unsigned long long)__double2ll_rn((double)p * FIXSCALE);
        unsigned long long add = (q & ~CNT_MASK) | 1ULL;

        unsigned long long old = atomicAdd(&g_acc, add);
        if ((old & CNT_MASK) == (unsigned long long)(BLOCKS - 1)) {
            // We are the last arriver; old + add is the complete total.
            unsigned long long total = (old + add) & ~CNT_MASK;
            double sum = (double)total * (1.0 / FIXSCALE);
            out[0] = (float)(sum / (double)TOTAL_PIX);
            g_acc = 0ULL;   // reset for next graph replay
        }
    }
}

extern "C" void kernel_launch(void* const* d_in, const int* in_sizes, int n_in,
                              void* d_out, int out_size) {
    const float* X = (const float*)d_in[0];
    const float* Y = (const float*)d_in[1];
    float* out = (float*)d_out;

    msfa_charbonnier_fused<<<BLOCKS, THREADS>>>(X, Y, out);
}